// round 9
// baseline (speedup 1.0000x reference)
#include <cuda_runtime.h>

#define FULLMASK 0xffffffffu
#define P 6
#define NWARP 10
// Per-point scratch (floats): sh/scr[64] + sp[16] + sA/u2[288] (A rows padded to 18)
#define WS_PT 368

typedef unsigned long long u64;

__device__ __forceinline__ u64 pk2(float lo, float hi) {
    u64 r; asm("mov.b64 %0, {%1,%2};" : "=l"(r) : "f"(lo), "f"(hi)); return r;
}
__device__ __forceinline__ void unpk(u64 a, float& lo, float& hi) {
    asm("mov.b64 {%0,%1}, %2;" : "=f"(lo), "=f"(hi) : "l"(a));
}
__device__ __forceinline__ u64 ffma2(u64 a, u64 b, u64 c) {
    u64 d; asm("fma.rn.f32x2 %0, %1, %2, %3;" : "=l"(d) : "l"(a), "l"(b), "l"(c)); return d;
}
__device__ __forceinline__ float tanh_fast(float x) {
    float y; asm("tanh.approx.f32 %0, %1;" : "=f"(y) : "f"(x)); return y;
}

// Dual width-16 Gaussian elimination (two independent SPD systems, interleaved).
__device__ __forceinline__ void solve16_dual(
    float ga[16], float ra, float gb[16], float rb, int l16, float& ya_o, float& yb_o)
{
    #pragma unroll
    for (int k = 0; k < 16; ++k) {
        float pva = __shfl_sync(FULLMASK, ga[k], k, 16);
        float pvb = __shfl_sync(FULLMASK, gb[k], k, 16);
        float pra = __shfl_sync(FULLMASK, ra,    k, 16);
        float prb = __shfl_sync(FULLMASK, rb,    k, 16);
        float fa = __fdividef(ga[k], pva);
        float fb = __fdividef(gb[k], pvb);
        bool act = (l16 > k);
        #pragma unroll
        for (int j = k + 1; j < 16; ++j) {
            float pja = __shfl_sync(FULLMASK, ga[j], k, 16);
            float pjb = __shfl_sync(FULLMASK, gb[j], k, 16);
            if (act) {
                ga[j] = fmaf(-fa, pja, ga[j]);
                gb[j] = fmaf(-fb, pjb, gb[j]);
            }
        }
        if (act) {
            ra = fmaf(-fa, pra, ra);
            rb = fmaf(-fb, prb, rb);
        }
    }
    float ya = 0.f, yb = 0.f;
    #pragma unroll
    for (int k = 15; k >= 0; --k) {
        float dka = __shfl_sync(FULLMASK, ga[k], k, 16);
        float dkb = __shfl_sync(FULLMASK, gb[k], k, 16);
        float rka = __shfl_sync(FULLMASK, ra,    k, 16);
        float rkb = __shfl_sync(FULLMASK, rb,    k, 16);
        float yka = __fdividef(rka, dka);
        float ykb = __fdividef(rkb, dkb);
        if (l16 == k) { ya = yka; yb = ykb; }
        if (l16 < k) {
            ra = fmaf(-ga[k], yka, ra);
            rb = fmaf(-gb[k], ykb, rb);
        }
    }
    ya_o = ya; yb_o = yb;
}

// Single pair-packed width-16 solve (dual solver minus the second system).
__device__ __forceinline__ float solve16_one(float ga[16], float ra, int l16)
{
    #pragma unroll
    for (int k = 0; k < 16; ++k) {
        float pva = __shfl_sync(FULLMASK, ga[k], k, 16);
        float pra = __shfl_sync(FULLMASK, ra,    k, 16);
        float fa = __fdividef(ga[k], pva);
        bool act = (l16 > k);
        #pragma unroll
        for (int j = k + 1; j < 16; ++j) {
            float pja = __shfl_sync(FULLMASK, ga[j], k, 16);
            if (act) ga[j] = fmaf(-fa, pja, ga[j]);
        }
        if (act) ra = fmaf(-fa, pra, ra);
    }
    float ya = 0.f;
    #pragma unroll
    for (int k = 15; k >= 0; --k) {
        float dka = __shfl_sync(FULLMASK, ga[k], k, 16);
        float rka = __shfl_sync(FULLMASK, ra,    k, 16);
        float yka = __fdividef(rka, dka);
        if (l16 == k) ya = yka;
        if (l16 < k)  ra = fmaf(-ga[k], yka, ra);
    }
    return ya;
}

// Evaluate geodesic ODE RHS for P=6 points (one warp).
__device__ __forceinline__ void warp_f6(
    const float zt[P], float kout[P], int lane,
    const float* __restrict__ sW1p, const float* __restrict__ sW1Tp,
    const float* __restrict__ sW2u, const float* __restrict__ sb1,
    const float* __restrict__ sb2, float* ws)
{
    float* sh[P]; float* sp[P]; float* sA[P];
    #pragma unroll
    for (int p = 0; p < P; ++p) {
        float* b = ws + p * WS_PT;
        sh[p] = b;         // 64  (aliased: scr overwrites after row-pass)
        sp[p] = b + 64;    // 16
        sA[p] = b + 80;    // 16*18 = 288 (aliased: u2[128 u64] overwrites after g-pass)
    }

    // ---- h = tanh(x W1 + b1); W1 loads hoisted over p ----
    const u64* w1p = (const u64*)sW1p;
    u64 pre2[P];
    {
        u64 b0 = pk2(sb1[lane], sb1[lane + 32]);
        #pragma unroll
        for (int p = 0; p < P; ++p) pre2[p] = b0;
    }
    #pragma unroll
    for (int i = 0; i < 16; ++i) {
        u64 w = w1p[i * 32 + lane];
        #pragma unroll
        for (int p = 0; p < P; ++p) {
            float xi = __shfl_sync(FULLMASK, zt[p], i);
            pre2[p] = ffma2(pk2(xi, xi), w, pre2[p]);
        }
    }
    float c0[P], c1[P];
    #pragma unroll
    for (int p = 0; p < P; ++p) {
        float pr0, pr1; unpk(pre2[p], pr0, pr1);
        float h0 = tanh_fast(pr0), h1 = tanh_fast(pr1);
        sh[p][lane]      = h0;  sh[p][lane + 32] = h1;
        c0[p] = 1.f - h0 * h0;
        c1[p] = 1.f - h1 * h1;
    }
    __syncwarp();

    // ---- W2 col-pass: A = h W2 + b2 (pair layout, 130-u64 row stride) ----
    u64 aA2[P][4];
    #pragma unroll
    for (int t2 = 0; t2 < 4; ++t2) {
        u64 bv = pk2(sb2[lane + 64 * t2], sb2[lane + 64 * t2 + 32]);
        #pragma unroll
        for (int p = 0; p < P; ++p) aA2[p][t2] = bv;
    }
    const u64* w2u = (const u64*)sW2u;
    #pragma unroll 2
    for (int j = 0; j < 64; j += 4) {
        float4 hq[P];
        #pragma unroll
        for (int p = 0; p < P; ++p) hq[p] = *(const float4*)&sh[p][j];
        #pragma unroll
        for (int jj = 0; jj < 4; ++jj) {
            const u64* wrp = w2u + (j + jj) * 130 + lane;
            u64 w[4];
            #pragma unroll
            for (int t2 = 0; t2 < 4; ++t2) w[t2] = wrp[t2 * 32];
            #pragma unroll
            for (int p = 0; p < P; ++p) {
                float hv = (jj == 0) ? hq[p].x : (jj == 1) ? hq[p].y
                         : (jj == 2) ? hq[p].z : hq[p].w;
                u64 h2 = pk2(hv, hv);
                #pragma unroll
                for (int t2 = 0; t2 < 4; ++t2)
                    aA2[p][t2] = ffma2(h2, w[t2], aA2[p][t2]);
            }
        }
    }

    // ---- p_b = sum_a v_a A[a,b] (v re-shuffled from zt); store p and A (pad 18) ----
    #pragma unroll
    for (int p = 0; p < P; ++p) {
        u64 pp2 = 0ull;
        #pragma unroll
        for (int t2 = 0; t2 < 4; ++t2) {
            int a0 = (lane >> 4) + 4 * t2;
            float v0 = __shfl_sync(FULLMASK, zt[p], 16 + a0);
            float v1 = __shfl_sync(FULLMASK, zt[p], 16 + a0 + 2);
            pp2 = ffma2(pk2(v0, v1), aA2[p][t2], pp2);
        }
        float pl, ph; unpk(pp2, pl, ph);
        float pp = pl + ph;
        pp += __shfl_xor_sync(FULLMASK, pp, 16);
        if (lane < 16) sp[p][lane] = pp;
        int bcol = lane & 15;
        #pragma unroll
        for (int t2 = 0; t2 < 4; ++t2) {
            int a0 = (lane >> 4) + 4 * t2;
            float alo, ahi; unpk(aA2[p][t2], alo, ahi);
            sA[p][a0 * 18 + bcol]       = alo;
            sA[p][(a0 + 2) * 18 + bcol] = ahi;
        }
    }
    __syncwarp();

    // ---- g = A A^T + I ; lane (row = lane&15) computes cols [8*(lane>>4), +8) ----
    int rrow = lane & 15;
    int cg   = (lane >> 4) * 8;
    float gp[P][8];
    #pragma unroll
    for (int p = 0; p < P; ++p) {
        u64 Ar2[8];
        #pragma unroll
        for (int c2 = 0; c2 < 8; ++c2)
            Ar2[c2] = *(const u64*)&sA[p][rrow * 18 + 2 * c2];
        #pragma unroll
        for (int t = 0; t < 8; ++t) {
            u64 acc2 = 0ull;
            #pragma unroll
            for (int c2 = 0; c2 < 8; ++c2) {
                u64 o = *(const u64*)&sA[p][(cg + t) * 18 + 2 * c2];
                acc2 = ffma2(Ar2[c2], o, acc2);
            }
            float al, ah; unpk(acc2, al, ah);
            gp[p][t] = al + ah + ((cg + t == rrow) ? 1.f : 0.f);
        }
    }
    __syncwarp();   // all sA reads done before u2 overwrites

    // ---- build u2 (pair layout matching W2): u2[t2*32+lane] = (v0*pb, v1*pb) ----
    #pragma unroll
    for (int p = 0; p < P; ++p) {
        float pb = sp[p][lane & 15];
        u64* u2p = (u64*)sA[p];
        #pragma unroll
        for (int t2 = 0; t2 < 4; ++t2) {
            int a0 = (lane >> 4) + 4 * t2;
            float v0 = __shfl_sync(FULLMASK, zt[p], 16 + a0);
            float v1 = __shfl_sync(FULLMASK, zt[p], 16 + a0 + 2);
            u2p[t2 * 32 + lane] = pk2(v0 * pb, v1 * pb);
        }
    }
    __syncwarp();

    // ---- W2 row-pass: m_j = sum_m W2pair[j,m].u2[m] ; lane owns j=lane, lane+32 ----
    u64 mj0[P], mj1[P];
    #pragma unroll
    for (int p = 0; p < P; ++p) { mj0[p] = 0ull; mj1[p] = 0ull; }
    const u64* r0 = w2u + lane * 130;
    const u64* r1 = w2u + (lane + 32) * 130;
    #pragma unroll 4
    for (int m2 = 0; m2 < 64; ++m2) {
        float4 w0q = *(const float4*)(r0 + 2 * m2);
        float4 w1q = *(const float4*)(r1 + 2 * m2);
        u64 w0a = pk2(w0q.x, w0q.y), w0b = pk2(w0q.z, w0q.w);
        u64 w1a = pk2(w1q.x, w1q.y), w1b = pk2(w1q.z, w1q.w);
        #pragma unroll
        for (int p = 0; p < P; ++p) {
            float4 uu = *(const float4*)((const float*)sA[p] + 4 * m2);  // broadcast
            u64 ua = pk2(uu.x, uu.y), ub = pk2(uu.z, uu.w);
            mj0[p] = ffma2(ua, w0a, mj0[p]);
            mj0[p] = ffma2(ub, w0b, mj0[p]);
            mj1[p] = ffma2(ua, w1a, mj1[p]);
            mj1[p] = ffma2(ub, w1b, mj1[p]);
        }
    }
    // scr_j = c_j * m_j  (scr aliases sh)
    #pragma unroll
    for (int p = 0; p < P; ++p) {
        float a, b;
        unpk(mj0[p], a, b); sh[p][lane]      = c0[p] * (a + b);
        unpk(mj1[p], a, b); sh[p][lane + 32] = c1[p] * (a + b);
    }
    __syncwarp();

    // ---- s_i = sum_j W1[i,j]*scr[j] (contiguous-half split + xor16 combine) ----
    float ssum[P];
    int irow = lane & 15, jo = lane >> 4;
    const u64* w1tp = (const u64*)sW1Tp;
    #pragma unroll
    for (int p = 0; p < P; ++p) {
        u64 s2 = 0ull;
        #pragma unroll
        for (int j2l = 0; j2l < 16; ++j2l) {
            int j2 = jo * 16 + j2l;
            s2 = ffma2(w1tp[j2 * 16 + irow], *(const u64*)&sh[p][2 * j2], s2);
        }
        float sl, shi; unpk(s2, sl, shi);
        float s = sl + shi;
        s += __shfl_xor_sync(FULLMASK, s, 16);
        ssum[p] = s;
    }
    // (factor 2 in s and 1/2 in Gamma cancel: solve g y = s, dv = -y)

    bool lo = lane < 16;
    int  l16 = lane & 15;

    // sysA: pts 0/1 pair-packed; sysB: pts 2/3; sysC: pts 4/5
    float ga[16], gb[16], gc[16];
    #pragma unroll
    for (int t = 0; t < 8; ++t) {
        float a0 = __shfl_xor_sync(FULLMASK, gp[0][t], 16);
        float a1 = __shfl_xor_sync(FULLMASK, gp[1][t], 16);
        float a2 = __shfl_xor_sync(FULLMASK, gp[2][t], 16);
        float a3 = __shfl_xor_sync(FULLMASK, gp[3][t], 16);
        float a4 = __shfl_xor_sync(FULLMASK, gp[4][t], 16);
        float a5 = __shfl_xor_sync(FULLMASK, gp[5][t], 16);
        ga[t]     = lo ? gp[0][t] : a1;
        ga[8 + t] = lo ? a0       : gp[1][t];
        gb[t]     = lo ? gp[2][t] : a3;
        gb[8 + t] = lo ? a2       : gp[3][t];
        gc[t]     = lo ? gp[4][t] : a5;
        gc[8 + t] = lo ? a4       : gp[5][t];
    }
    float ra = lo ? ssum[0] : ssum[1];
    float rb = lo ? ssum[2] : ssum[3];
    float rc = lo ? ssum[4] : ssum[5];

    float y01, y23;
    solve16_dual(ga, ra, gb, rb, l16, y01, y23);
    float y45 = solve16_one(gc, rc, l16);

    // ---- assemble k: lane<16 -> v part, lane>=16 -> dv = -y ----
    kout[0] = __shfl_xor_sync(FULLMASK, lo ? -y01 : zt[0], 16);
    float t1s = __shfl_xor_sync(FULLMASK, zt[1], 16);
    kout[1] = lo ? t1s : -y01;
    kout[2] = __shfl_xor_sync(FULLMASK, lo ? -y23 : zt[2], 16);
    float t3s = __shfl_xor_sync(FULLMASK, zt[3], 16);
    kout[3] = lo ? t3s : -y23;
    kout[4] = __shfl_xor_sync(FULLMASK, lo ? -y45 : zt[4], 16);
    float t5s = __shfl_xor_sync(FULLMASK, zt[5], 16);
    kout[5] = lo ? t5s : -y45;
    __syncwarp();
}

extern __shared__ float smem_dyn[];

__global__ void __launch_bounds__(NWARP * 32, 1)
geo_kernel(const float* __restrict__ z_in,
           const float* __restrict__ t_ptr,
           const float* __restrict__ W1,
           const float* __restrict__ b1,
           const float* __restrict__ W2,
           const float* __restrict__ b2,
           const int*   __restrict__ ns_ptr,
           float* __restrict__ z_out,
           int B)
{
    float* sW1p  = smem_dyn;           // u64 pairs (W1[i,l], W1[i,l+32]) at u64-idx i*32+l
    float* sW1Tp = smem_dyn + 1024;    // u64 pairs (W1[i,2j2], W1[i,2j2+1]) at u64-idx j2*16+i
    float* sW2u  = smem_dyn + 2048;    // u64 pairs (W2[j,l+64t2], W2[j,l+64t2+32]) at u64-idx j*130+t2*32+l
    float* sb1   = smem_dyn + 18688;   // 64
    float* sb2   = smem_dyn + 18752;   // 256
    float* wsbase = smem_dyn + 19008;  // NWARP * P * WS_PT

    int tid = threadIdx.x;
    const int NT = NWARP * 32;
    for (int idx = tid; idx < 1024; idx += NT) {
        float w = W1[idx];
        int i = idx >> 6, j = idx & 63;
        sW1p [2 * (i * 32 + (j & 31)) + (j >> 5)] = w;
        sW1Tp[2 * ((j >> 1) * 16 + i) + (j & 1)]  = w;
    }
    for (int idx = tid; idx < 16384; idx += NT) {
        float w = W2[idx];
        int j = idx >> 8, c = idx & 255;
        int tt = c >> 5, l = c & 31;
        sW2u[2 * (j * 130 + (tt >> 1) * 32 + l) + (tt & 1)] = w;
    }
    if (tid < 64) sb1[tid] = b1[tid];
    if (tid < 256) sb2[tid] = b2[tid];
    __syncthreads();

    int warp = tid >> 5, lane = tid & 31;
    float* ws = wsbase + warp * (P * WS_PT);

    int pt0 = (blockIdx.x * NWARP + warp) * P;
    float z[P];
    #pragma unroll
    for (int p = 0; p < P; ++p) {
        int pt = pt0 + p;
        z[p] = (pt < B) ? z_in[pt * 32 + lane] : 0.f;
    }

    int ns = ns_ptr[0];
    float dt = t_ptr[0] / (float)ns;

    float kk[P], acc[P], zt[P];
    #pragma unroll 1
    for (int step = 0; step < ns; ++step) {
        #pragma unroll
        for (int p = 0; p < P; ++p) { kk[p] = 0.f; acc[p] = 0.f; }
        #pragma unroll 1
        for (int s = 0; s < 4; ++s) {
            float alpha = (s == 0) ? 0.f : ((s == 3) ? 1.f : 0.5f);
            float wgt   = (s == 1 || s == 2) ? 2.f : 1.f;
            #pragma unroll
            for (int p = 0; p < P; ++p) zt[p] = fmaf(alpha * dt, kk[p], z[p]);
            warp_f6(zt, kk, lane, sW1p, sW1Tp, sW2u, sb1, sb2, ws);
            #pragma unroll
            for (int p = 0; p < P; ++p) acc[p] += wgt * kk[p];
        }
        #pragma unroll
        for (int p = 0; p < P; ++p) z[p] = fmaf(dt / 6.f, acc[p], z[p]);
    }

    #pragma unroll
    for (int p = 0; p < P; ++p) {
        int pt = pt0 + p;
        if (pt < B) z_out[pt * 32 + lane] = z[p];
    }
}

extern "C" void kernel_launch(void* const* d_in, const int* in_sizes, int n_in,
                              void* d_out, int out_size)
{
    const float* z  = (const float*)d_in[0];
    const float* t  = (const float*)d_in[1];
    const float* W1 = (const float*)d_in[2];
    const float* b1 = (const float*)d_in[3];
    const float* W2 = (const float*)d_in[4];
    const float* b2 = (const float*)d_in[5];
    const int*   ns = (const int*)d_in[6];
    float* out = (float*)d_out;

    int B = in_sizes[0] / 32;                 // 16384 points
    int smem_bytes = (19008 + NWARP * P * WS_PT) * sizeof(float);  // 164,352 B

    cudaFuncSetAttribute(geo_kernel,
                         cudaFuncAttributeMaxDynamicSharedMemorySize, smem_bytes);

    int pts_per_block = NWARP * P;
    int blocks = (B + pts_per_block - 1) / pts_per_block;
    geo_kernel<<<blocks, NWARP * 32, smem_bytes>>>(z, t, W1, b1, W2, b2, ns, out, B);
}

// round 13
// speedup vs baseline: 1.0736x; 1.0736x over previous
#include <cuda_runtime.h>
#include <cuda_fp16.h>

#define FULLMASK 0xffffffffu
#define P 4
#define NWARP 14
// Per-point scratch (floats): sh/scr[64] + sA/u2[288] (A rows padded to 18)
#define WS_PT 352

typedef unsigned long long u64;

__device__ __forceinline__ u64 pk2(float lo, float hi) {
    u64 r; asm("mov.b64 %0, {%1,%2};" : "=l"(r) : "f"(lo), "f"(hi)); return r;
}
__device__ __forceinline__ void unpk(u64 a, float& lo, float& hi) {
    asm("mov.b64 {%0,%1}, %2;" : "=f"(lo), "=f"(hi) : "l"(a));
}
__device__ __forceinline__ u64 ffma2(u64 a, u64 b, u64 c) {
    u64 d; asm("fma.rn.f32x2 %0, %1, %2, %3;" : "=l"(d) : "l"(a), "l"(b), "l"(c)); return d;
}
__device__ __forceinline__ float tanh_fast(float x) {
    float y; asm("tanh.approx.f32 %0, %1;" : "=f"(y) : "f"(x)); return y;
}
// half2 (packed u32) -> f32x2 operand
__device__ __forceinline__ u64 hpk(unsigned int u) {
    __half2 h = *reinterpret_cast<const __half2*>(&u);
    float2 f = __half22float2(h);
    return pk2(f.x, f.y);
}

// Dual width-16 Gaussian elimination (two independent SPD systems, interleaved).
__device__ __forceinline__ void solve16_dual(
    float ga[16], float ra, float gb[16], float rb, int l16, float& ya_o, float& yb_o)
{
    #pragma unroll
    for (int k = 0; k < 16; ++k) {
        float pva = __shfl_sync(FULLMASK, ga[k], k, 16);
        float pvb = __shfl_sync(FULLMASK, gb[k], k, 16);
        float pra = __shfl_sync(FULLMASK, ra,    k, 16);
        float prb = __shfl_sync(FULLMASK, rb,    k, 16);
        float fa = __fdividef(ga[k], pva);
        float fb = __fdividef(gb[k], pvb);
        bool act = (l16 > k);
        #pragma unroll
        for (int j = k + 1; j < 16; ++j) {
            float pja = __shfl_sync(FULLMASK, ga[j], k, 16);
            float pjb = __shfl_sync(FULLMASK, gb[j], k, 16);
            if (act) {
                ga[j] = fmaf(-fa, pja, ga[j]);
                gb[j] = fmaf(-fb, pjb, gb[j]);
            }
        }
        if (act) {
            ra = fmaf(-fa, pra, ra);
            rb = fmaf(-fb, prb, rb);
        }
    }
    float ya = 0.f, yb = 0.f;
    #pragma unroll
    for (int k = 15; k >= 0; --k) {
        float dka = __shfl_sync(FULLMASK, ga[k], k, 16);
        float dkb = __shfl_sync(FULLMASK, gb[k], k, 16);
        float rka = __shfl_sync(FULLMASK, ra,    k, 16);
        float rkb = __shfl_sync(FULLMASK, rb,    k, 16);
        float yka = __fdividef(rka, dka);
        float ykb = __fdividef(rkb, dkb);
        if (l16 == k) { ya = yka; yb = ykb; }
        if (l16 < k) {
            ra = fmaf(-ga[k], yka, ra);
            rb = fmaf(-gb[k], ykb, rb);
        }
    }
    ya_o = ya; yb_o = yb;
}

// Evaluate geodesic ODE RHS for P=4 points (one warp).
__device__ __forceinline__ void warp_f4(
    const float zt[P], float kout[P], int lane,
    const float* __restrict__ sW1p, const float* __restrict__ sW1Tp,
    const unsigned int* __restrict__ sW2h, const float* __restrict__ sb1,
    const float* __restrict__ sb2, float* ws)
{
    float* sh[P]; float* sA[P];
    #pragma unroll
    for (int p = 0; p < P; ++p) {
        float* b = ws + p * WS_PT;
        sh[p] = b;         // 64  (aliased: scr overwrites after row-pass)
        sA[p] = b + 64;    // 16*18 = 288 (aliased: u2[128 u64] overwrites after g-pass)
    }

    // ---- h = tanh(x W1 + b1); W1 loads hoisted over p ----
    const u64* w1p = (const u64*)sW1p;
    u64 pre2[P];
    {
        u64 b0 = pk2(sb1[lane], sb1[lane + 32]);
        #pragma unroll
        for (int p = 0; p < P; ++p) pre2[p] = b0;
    }
    #pragma unroll
    for (int i = 0; i < 16; ++i) {
        u64 w = w1p[i * 32 + lane];
        #pragma unroll
        for (int p = 0; p < P; ++p) {
            float xi = __shfl_sync(FULLMASK, zt[p], i);
            pre2[p] = ffma2(pk2(xi, xi), w, pre2[p]);
        }
    }
    float c0[P], c1[P];
    #pragma unroll
    for (int p = 0; p < P; ++p) {
        float pr0, pr1; unpk(pre2[p], pr0, pr1);
        float h0 = tanh_fast(pr0), h1 = tanh_fast(pr1);
        sh[p][lane]      = h0;  sh[p][lane + 32] = h1;
        c0[p] = 1.f - h0 * h0;
        c1[p] = 1.f - h1 * h1;
    }
    __syncwarp();

    // ---- W2 col-pass: A = h W2 + b2 (fp16 pair layout, 132-u32 row stride) ----
    u64 aA2[P][4];
    #pragma unroll
    for (int t2 = 0; t2 < 4; ++t2) {
        u64 bv = pk2(sb2[lane + 64 * t2], sb2[lane + 64 * t2 + 32]);
        #pragma unroll
        for (int p = 0; p < P; ++p) aA2[p][t2] = bv;
    }
    #pragma unroll 2
    for (int j = 0; j < 64; j += 4) {
        float4 hq[P];
        #pragma unroll
        for (int p = 0; p < P; ++p) hq[p] = *(const float4*)&sh[p][j];
        #pragma unroll
        for (int jj = 0; jj < 4; ++jj) {
            const unsigned int* wrp = sW2h + (j + jj) * 132 + lane;
            u64 w[4];
            #pragma unroll
            for (int t2 = 0; t2 < 4; ++t2) w[t2] = hpk(wrp[t2 * 32]);
            #pragma unroll
            for (int p = 0; p < P; ++p) {
                float hv = (jj == 0) ? hq[p].x : (jj == 1) ? hq[p].y
                         : (jj == 2) ? hq[p].z : hq[p].w;
                u64 h2 = pk2(hv, hv);
                #pragma unroll
                for (int t2 = 0; t2 < 4; ++t2)
                    aA2[p][t2] = ffma2(h2, w[t2], aA2[p][t2]);
            }
        }
    }

    // ---- p_b = sum_a v_a A[a,b]; after xor16 every lane holds p_{lane&15} ----
    float ppv[P];
    #pragma unroll
    for (int p = 0; p < P; ++p) {
        u64 pp2 = 0ull;
        #pragma unroll
        for (int t2 = 0; t2 < 4; ++t2) {
            int a0 = (lane >> 4) + 4 * t2;
            float v0 = __shfl_sync(FULLMASK, zt[p], 16 + a0);
            float v1 = __shfl_sync(FULLMASK, zt[p], 16 + a0 + 2);
            pp2 = ffma2(pk2(v0, v1), aA2[p][t2], pp2);
        }
        float pl, ph; unpk(pp2, pl, ph);
        float pp = pl + ph;
        pp += __shfl_xor_sync(FULLMASK, pp, 16);
        ppv[p] = pp;
        int bcol = lane & 15;
        #pragma unroll
        for (int t2 = 0; t2 < 4; ++t2) {
            int a0 = (lane >> 4) + 4 * t2;
            float alo, ahi; unpk(aA2[p][t2], alo, ahi);
            sA[p][a0 * 18 + bcol]       = alo;
            sA[p][(a0 + 2) * 18 + bcol] = ahi;
        }
    }
    __syncwarp();

    // ---- g = A A^T + I ; lane (row = lane&15) computes cols [8*(lane>>4), +8) ----
    int rrow = lane & 15;
    int cg   = (lane >> 4) * 8;
    float gp[P][8];
    #pragma unroll
    for (int p = 0; p < P; ++p) {
        u64 Ar2[8];
        #pragma unroll
        for (int c2 = 0; c2 < 8; ++c2)
            Ar2[c2] = *(const u64*)&sA[p][rrow * 18 + 2 * c2];
        #pragma unroll
        for (int t = 0; t < 8; ++t) {
            u64 acc2 = 0ull;
            #pragma unroll
            for (int c2 = 0; c2 < 8; ++c2) {
                u64 o = *(const u64*)&sA[p][(cg + t) * 18 + 2 * c2];
                acc2 = ffma2(Ar2[c2], o, acc2);
            }
            float al, ah; unpk(acc2, al, ah);
            gp[p][t] = al + ah + ((cg + t == rrow) ? 1.f : 0.f);
        }
    }
    __syncwarp();   // all sA reads done before u2 overwrites

    // ---- build u2 (pair layout matching W2): u2[t2*32+lane] = (v0*pb, v1*pb) ----
    #pragma unroll
    for (int p = 0; p < P; ++p) {
        float pb = ppv[p];                 // p_{lane&15}, resident on every lane
        u64* u2p = (u64*)sA[p];
        #pragma unroll
        for (int t2 = 0; t2 < 4; ++t2) {
            int a0 = (lane >> 4) + 4 * t2;
            float v0 = __shfl_sync(FULLMASK, zt[p], 16 + a0);
            float v1 = __shfl_sync(FULLMASK, zt[p], 16 + a0 + 2);
            u2p[t2 * 32 + lane] = pk2(v0 * pb, v1 * pb);
        }
    }
    __syncwarp();

    // ---- W2 row-pass (fp16): m_j = sum_m W2pair[j,m].u2[m] ; lane owns j=lane, lane+32 ----
    u64 mj0[P], mj1[P];
    #pragma unroll
    for (int p = 0; p < P; ++p) { mj0[p] = 0ull; mj1[p] = 0ull; }
    const unsigned int* r0h = sW2h + lane * 132;
    const unsigned int* r1h = sW2h + (lane + 32) * 132;
    #pragma unroll 4
    for (int m4 = 0; m4 < 32; ++m4) {
        uint4 w0 = *(const uint4*)(r0h + 4 * m4);
        uint4 w1 = *(const uint4*)(r1h + 4 * m4);
        u64 w0p[4] = {hpk(w0.x), hpk(w0.y), hpk(w0.z), hpk(w0.w)};
        u64 w1p4[4] = {hpk(w1.x), hpk(w1.y), hpk(w1.z), hpk(w1.w)};
        #pragma unroll
        for (int p = 0; p < P; ++p) {
            const float* uf = (const float*)sA[p];
            float4 ua4 = *(const float4*)(uf + 8 * m4);        // pairs 4m4, 4m4+1
            float4 ub4 = *(const float4*)(uf + 8 * m4 + 4);    // pairs 4m4+2, 4m4+3
            u64 u0 = pk2(ua4.x, ua4.y), u1 = pk2(ua4.z, ua4.w);
            u64 u2v = pk2(ub4.x, ub4.y), u3 = pk2(ub4.z, ub4.w);
            mj0[p] = ffma2(u0, w0p[0], mj0[p]);
            mj0[p] = ffma2(u1, w0p[1], mj0[p]);
            mj0[p] = ffma2(u2v, w0p[2], mj0[p]);
            mj0[p] = ffma2(u3, w0p[3], mj0[p]);
            mj1[p] = ffma2(u0, w1p4[0], mj1[p]);
            mj1[p] = ffma2(u1, w1p4[1], mj1[p]);
            mj1[p] = ffma2(u2v, w1p4[2], mj1[p]);
            mj1[p] = ffma2(u3, w1p4[3], mj1[p]);
        }
    }
    // scr_j = c_j * m_j  (scr aliases sh)
    #pragma unroll
    for (int p = 0; p < P; ++p) {
        float a, b;
        unpk(mj0[p], a, b); sh[p][lane]      = c0[p] * (a + b);
        unpk(mj1[p], a, b); sh[p][lane + 32] = c1[p] * (a + b);
    }
    __syncwarp();

    // ---- s_i = sum_j W1[i,j]*scr[j] (contiguous-half split + xor16 combine) ----
    float ssum[P];
    int irow = lane & 15, jo = lane >> 4;
    const u64* w1tp = (const u64*)sW1Tp;
    #pragma unroll
    for (int p = 0; p < P; ++p) {
        u64 s2 = 0ull;
        #pragma unroll
        for (int j2l = 0; j2l < 16; ++j2l) {
            int j2 = jo * 16 + j2l;
            s2 = ffma2(w1tp[j2 * 16 + irow], *(const u64*)&sh[p][2 * j2], s2);
        }
        float sl, shi; unpk(s2, sl, shi);
        float s = sl + shi;
        s += __shfl_xor_sync(FULLMASK, s, 16);
        ssum[p] = s;
    }
    // (factor 2 in s and 1/2 in Gamma cancel: solve g y = s, dv = -y)

    bool lo = lane < 16;
    int  l16 = lane & 15;

    // sysA: pts 0/1 pair-packed; sysB: pts 2/3 pair-packed
    float ga[16], gb[16];
    #pragma unroll
    for (int t = 0; t < 8; ++t) {
        float a0 = __shfl_xor_sync(FULLMASK, gp[0][t], 16);
        float a1 = __shfl_xor_sync(FULLMASK, gp[1][t], 16);
        float a2 = __shfl_xor_sync(FULLMASK, gp[2][t], 16);
        float a3 = __shfl_xor_sync(FULLMASK, gp[3][t], 16);
        ga[t]     = lo ? gp[0][t] : a1;
        ga[8 + t] = lo ? a0       : gp[1][t];
        gb[t]     = lo ? gp[2][t] : a3;
        gb[8 + t] = lo ? a2       : gp[3][t];
    }
    float ra = lo ? ssum[0] : ssum[1];
    float rb = lo ? ssum[2] : ssum[3];

    float y01, y23;
    solve16_dual(ga, ra, gb, rb, l16, y01, y23);

    // ---- assemble k: lane<16 -> v part, lane>=16 -> dv = -y ----
    kout[0] = __shfl_xor_sync(FULLMASK, lo ? -y01 : zt[0], 16);
    float t1s = __shfl_xor_sync(FULLMASK, zt[1], 16);
    kout[1] = lo ? t1s : -y01;
    kout[2] = __shfl_xor_sync(FULLMASK, lo ? -y23 : zt[2], 16);
    float t3s = __shfl_xor_sync(FULLMASK, zt[3], 16);
    kout[3] = lo ? t3s : -y23;
    __syncwarp();
}

extern __shared__ float smem_dyn[];

__global__ void __launch_bounds__(NWARP * 32, 1)
geo_kernel(const float* __restrict__ z_in,
           const float* __restrict__ t_ptr,
           const float* __restrict__ W1,
           const float* __restrict__ b1,
           const float* __restrict__ W2,
           const float* __restrict__ b2,
           const int*   __restrict__ ns_ptr,
           float* __restrict__ z_out,
           int B)
{
    // Layout (floats): sW1p [0,1024) ; sW1Tp [1024,2048) ; sW2h [2048,10496) (8448 u32)
    //                  sb1 [10496,10560) ; sb2 [10560,10816) ; wsbase [10816, ...)
    float* sW1p  = smem_dyn;           // u64 pairs (W1[i,l], W1[i,l+32]) at u64-idx i*32+l
    float* sW1Tp = smem_dyn + 1024;    // u64 pairs (W1[i,2j2], W1[i,2j2+1]) at u64-idx j2*16+i
    unsigned int* sW2h = (unsigned int*)(smem_dyn + 2048);  // half2 (W2[j,c],W2[j,c+32]) at u32-idx j*132+m
    float* sb1   = smem_dyn + 10496;   // 64
    float* sb2   = smem_dyn + 10560;   // 256
    float* wsbase = smem_dyn + 10816;  // NWARP * P * WS_PT

    int tid = threadIdx.x;
    const int NT = NWARP * 32;
    for (int idx = tid; idx < 1024; idx += NT) {
        float w = W1[idx];
        int i = idx >> 6, j = idx & 63;
        sW1p [2 * (i * 32 + (j & 31)) + (j >> 5)] = w;
        sW1Tp[2 * ((j >> 1) * 16 + i) + (j & 1)]  = w;
    }
    for (int idx = tid; idx < 64 * 128; idx += NT) {
        int j = idx >> 7, m = idx & 127;
        int c = ((m >> 5) << 6) + (m & 31);
        __half h0 = __float2half_rn(W2[j * 256 + c]);
        __half h1 = __float2half_rn(W2[j * 256 + c + 32]);
        __half2 hh = __halves2half2(h0, h1);
        sW2h[j * 132 + m] = *reinterpret_cast<unsigned int*>(&hh);
    }
    if (tid < 64) sb1[tid] = b1[tid];
    if (tid < 256) sb2[tid] = b2[tid];
    __syncthreads();

    int warp = tid >> 5, lane = tid & 31;
    float* ws = wsbase + warp * (P * WS_PT);

    int pt0 = (blockIdx.x * NWARP + warp) * P;
    float z[P];
    #pragma unroll
    for (int p = 0; p < P; ++p) {
        int pt = pt0 + p;
        z[p] = (pt < B) ? z_in[pt * 32 + lane] : 0.f;
    }

    int ns = ns_ptr[0];
    float dt = t_ptr[0] / (float)ns;

    float kk[P], acc[P], zt[P];
    #pragma unroll 1
    for (int step = 0; step < ns; ++step) {
        #pragma unroll
        for (int p = 0; p < P; ++p) { kk[p] = 0.f; acc[p] = 0.f; }
        #pragma unroll 1
        for (int s = 0; s < 4; ++s) {
            float alpha = (s == 0) ? 0.f : ((s == 3) ? 1.f : 0.5f);
            float wgt   = (s == 1 || s == 2) ? 2.f : 1.f;
            #pragma unroll
            for (int p = 0; p < P; ++p) zt[p] = fmaf(alpha * dt, kk[p], z[p]);
            warp_f4(zt, kk, lane, sW1p, sW1Tp, sW2h, sb1, sb2, ws);
            #pragma unroll
            for (int p = 0; p < P; ++p) acc[p] += wgt * kk[p];
        }
        #pragma unroll
        for (int p = 0; p < P; ++p) z[p] = fmaf(dt / 6.f, acc[p], z[p]);
    }

    #pragma unroll
    for (int p = 0; p < P; ++p) {
        int pt = pt0 + p;
        if (pt < B) z_out[pt * 32 + lane] = z[p];
    }
}

extern "C" void kernel_launch(void* const* d_in, const int* in_sizes, int n_in,
                              void* d_out, int out_size)
{
    const float* z  = (const float*)d_in[0];
    const float* t  = (const float*)d_in[1];
    const float* W1 = (const float*)d_in[2];
    const float* b1 = (const float*)d_in[3];
    const float* W2 = (const float*)d_in[4];
    const float* b2 = (const float*)d_in[5];
    const int*   ns = (const int*)d_in[6];
    float* out = (float*)d_out;

    int B = in_sizes[0] / 32;                 // 16384 points
    int smem_bytes = (10816 + NWARP * P * WS_PT) * sizeof(float);  // 122,112 B

    cudaFuncSetAttribute(geo_kernel,
                         cudaFuncAttributeMaxDynamicSharedMemorySize, smem_bytes);

    int pts_per_block = NWARP * P;
    int blocks = (B + pts_per_block - 1) / pts_per_block;
    geo_kernel<<<blocks, NWARP * 32, smem_bytes>>>(z, t, W1, b1, W2, b2, ns, out, B);
}

// round 15
// speedup vs baseline: 1.0745x; 1.0008x over previous
#include <cuda_runtime.h>
#include <cuda_fp16.h>

#define FULLMASK 0xffffffffu
#define P 4
#define NWARP 14
// Per-point scratch (floats): sh/scr[64] + sA/u2[320] (A rows padded to 20)
#define WS_PT 384

typedef unsigned long long u64;

__device__ __forceinline__ u64 pk2(float lo, float hi) {
    u64 r; asm("mov.b64 %0, {%1,%2};" : "=l"(r) : "f"(lo), "f"(hi)); return r;
}
__device__ __forceinline__ void unpk(u64 a, float& lo, float& hi) {
    asm("mov.b64 {%0,%1}, %2;" : "=f"(lo), "=f"(hi) : "l"(a));
}
__device__ __forceinline__ u64 ffma2(u64 a, u64 b, u64 c) {
    u64 d; asm("fma.rn.f32x2 %0, %1, %2, %3;" : "=l"(d) : "l"(a), "l"(b), "l"(c)); return d;
}
__device__ __forceinline__ float tanh_fast(float x) {
    float y; asm("tanh.approx.f32 %0, %1;" : "=f"(y) : "f"(x)); return y;
}
// half2 (packed u32) -> f32x2 operand
__device__ __forceinline__ u64 hpk(unsigned int u) {
    __half2 h = *reinterpret_cast<const __half2*>(&u);
    float2 f = __half22float2(h);
    return pk2(f.x, f.y);
}

// Dual width-16 Gaussian elimination: each "system" holds one point in lanes 0-15
// and another in lanes 16-31 (width-16 shuffles) -> 4 points per call total.
__device__ __forceinline__ void solve16_dual(
    float ga[16], float ra, float gb[16], float rb, int l16, float& ya_o, float& yb_o)
{
    #pragma unroll
    for (int k = 0; k < 16; ++k) {
        float pva = __shfl_sync(FULLMASK, ga[k], k, 16);
        float pvb = __shfl_sync(FULLMASK, gb[k], k, 16);
        float pra = __shfl_sync(FULLMASK, ra,    k, 16);
        float prb = __shfl_sync(FULLMASK, rb,    k, 16);
        float fa = __fdividef(ga[k], pva);
        float fb = __fdividef(gb[k], pvb);
        bool act = (l16 > k);
        #pragma unroll
        for (int j = k + 1; j < 16; ++j) {
            float pja = __shfl_sync(FULLMASK, ga[j], k, 16);
            float pjb = __shfl_sync(FULLMASK, gb[j], k, 16);
            if (act) {
                ga[j] = fmaf(-fa, pja, ga[j]);
                gb[j] = fmaf(-fb, pjb, gb[j]);
            }
        }
        if (act) {
            ra = fmaf(-fa, pra, ra);
            rb = fmaf(-fb, prb, rb);
        }
    }
    float ya = 0.f, yb = 0.f;
    #pragma unroll
    for (int k = 15; k >= 0; --k) {
        float dka = __shfl_sync(FULLMASK, ga[k], k, 16);
        float dkb = __shfl_sync(FULLMASK, gb[k], k, 16);
        float rka = __shfl_sync(FULLMASK, ra,    k, 16);
        float rkb = __shfl_sync(FULLMASK, rb,    k, 16);
        float yka = __fdividef(rka, dka);
        float ykb = __fdividef(rkb, dkb);
        if (l16 == k) { ya = yka; yb = ykb; }
        if (l16 < k) {
            ra = fmaf(-ga[k], yka, ra);
            rb = fmaf(-gb[k], ykb, rb);
        }
    }
    ya_o = ya; yb_o = yb;
}

// Evaluate geodesic ODE RHS for P=4 points (one warp).
__device__ __forceinline__ void warp_f4(
    const float zt[P], float kout[P], int lane,
    const unsigned int* __restrict__ sW1h, const unsigned int* __restrict__ sW1Th,
    const unsigned int* __restrict__ sW2h, const float* __restrict__ sb1,
    const float* __restrict__ sb2, float* ws)
{
    float* sh[P]; float* sA[P];
    #pragma unroll
    for (int p = 0; p < P; ++p) {
        float* b = ws + p * WS_PT;
        sh[p] = b;         // 64  (aliased: scr overwrites after row-pass)
        sA[p] = b + 64;    // 16*20 = 320 (aliased: u2[128 u64] overwrites after g-pass)
    }

    // ---- h = tanh(x W1 + b1); W1 fp16, loads hoisted over p ----
    u64 pre2[P];
    {
        u64 b0 = pk2(sb1[lane], sb1[lane + 32]);
        #pragma unroll
        for (int p = 0; p < P; ++p) pre2[p] = b0;
    }
    #pragma unroll
    for (int i = 0; i < 16; ++i) {
        u64 w = hpk(sW1h[i * 32 + lane]);
        #pragma unroll
        for (int p = 0; p < P; ++p) {
            float xi = __shfl_sync(FULLMASK, zt[p], i);
            pre2[p] = ffma2(pk2(xi, xi), w, pre2[p]);
        }
    }
    float c0[P], c1[P];
    #pragma unroll
    for (int p = 0; p < P; ++p) {
        float pr0, pr1; unpk(pre2[p], pr0, pr1);
        float h0 = tanh_fast(pr0), h1 = tanh_fast(pr1);
        sh[p][lane]      = h0;  sh[p][lane + 32] = h1;
        c0[p] = 1.f - h0 * h0;
        c1[p] = 1.f - h1 * h1;
    }
    __syncwarp();

    // ---- W2 col-pass: A = h W2 + b2 (fp16 pair layout, 132-u32 row stride) ----
    u64 aA2[P][4];
    #pragma unroll
    for (int t2 = 0; t2 < 4; ++t2) {
        u64 bv = pk2(sb2[lane + 64 * t2], sb2[lane + 64 * t2 + 32]);
        #pragma unroll
        for (int p = 0; p < P; ++p) aA2[p][t2] = bv;
    }
    #pragma unroll 2
    for (int j = 0; j < 64; j += 4) {
        float4 hq[P];
        #pragma unroll
        for (int p = 0; p < P; ++p) hq[p] = *(const float4*)&sh[p][j];
        #pragma unroll
        for (int jj = 0; jj < 4; ++jj) {
            const unsigned int* wrp = sW2h + (j + jj) * 132 + lane;
            u64 w[4];
            #pragma unroll
            for (int t2 = 0; t2 < 4; ++t2) w[t2] = hpk(wrp[t2 * 32]);
            #pragma unroll
            for (int p = 0; p < P; ++p) {
                float hv = (jj == 0) ? hq[p].x : (jj == 1) ? hq[p].y
                         : (jj == 2) ? hq[p].z : hq[p].w;
                u64 h2 = pk2(hv, hv);
                #pragma unroll
                for (int t2 = 0; t2 < 4; ++t2)
                    aA2[p][t2] = ffma2(h2, w[t2], aA2[p][t2]);
            }
        }
    }

    // ---- p_b = sum_a v_a A[a,b]; after xor16 every lane holds p_{lane&15} ----
    float ppv[P];
    #pragma unroll
    for (int p = 0; p < P; ++p) {
        u64 pp2 = 0ull;
        #pragma unroll
        for (int t2 = 0; t2 < 4; ++t2) {
            int a0 = (lane >> 4) + 4 * t2;
            float v0 = __shfl_sync(FULLMASK, zt[p], 16 + a0);
            float v1 = __shfl_sync(FULLMASK, zt[p], 16 + a0 + 2);
            pp2 = ffma2(pk2(v0, v1), aA2[p][t2], pp2);
        }
        float pl, ph; unpk(pp2, pl, ph);
        float pp = pl + ph;
        pp += __shfl_xor_sync(FULLMASK, pp, 16);
        ppv[p] = pp;
        int bcol = lane & 15;
        #pragma unroll
        for (int t2 = 0; t2 < 4; ++t2) {
            int a0 = (lane >> 4) + 4 * t2;
            float alo, ahi; unpk(aA2[p][t2], alo, ahi);
            sA[p][a0 * 20 + bcol]       = alo;
            sA[p][(a0 + 2) * 20 + bcol] = ahi;
        }
    }
    __syncwarp();

    // ---- g = A A^T + I ; float4 loads on pad-20 rows ----
    int rrow = lane & 15;
    int cg   = (lane >> 4) * 8;
    float gp[P][8];
    #pragma unroll
    for (int p = 0; p < P; ++p) {
        u64 Ar2[8];
        #pragma unroll
        for (int c4 = 0; c4 < 4; ++c4) {
            float4 a4 = *(const float4*)&sA[p][rrow * 20 + 4 * c4];
            Ar2[2 * c4]     = pk2(a4.x, a4.y);
            Ar2[2 * c4 + 1] = pk2(a4.z, a4.w);
        }
        #pragma unroll
        for (int t = 0; t < 8; ++t) {
            const float* orow = &sA[p][(cg + t) * 20];
            u64 acc2 = 0ull;
            #pragma unroll
            for (int c4 = 0; c4 < 4; ++c4) {
                float4 o4 = *(const float4*)(orow + 4 * c4);
                acc2 = ffma2(Ar2[2 * c4],     pk2(o4.x, o4.y), acc2);
                acc2 = ffma2(Ar2[2 * c4 + 1], pk2(o4.z, o4.w), acc2);
            }
            float al, ah; unpk(acc2, al, ah);
            gp[p][t] = al + ah + ((cg + t == rrow) ? 1.f : 0.f);
        }
    }
    __syncwarp();   // all sA reads done before u2 overwrites

    // ---- build u2 (pair layout matching W2): u2[t2*32+lane] = (v0*pb, v1*pb) ----
    #pragma unroll
    for (int p = 0; p < P; ++p) {
        float pb = ppv[p];                 // p_{lane&15}, resident on every lane
        u64* u2p = (u64*)sA[p];
        #pragma unroll
        for (int t2 = 0; t2 < 4; ++t2) {
            int a0 = (lane >> 4) + 4 * t2;
            float v0 = __shfl_sync(FULLMASK, zt[p], 16 + a0);
            float v1 = __shfl_sync(FULLMASK, zt[p], 16 + a0 + 2);
            u2p[t2 * 32 + lane] = pk2(v0 * pb, v1 * pb);
        }
    }
    __syncwarp();

    // ---- W2 row-pass (fp16): m_j = sum_m W2pair[j,m].u2[m] ; lane owns j=lane, lane+32 ----
    u64 mj0[P], mj1[P];
    #pragma unroll
    for (int p = 0; p < P; ++p) { mj0[p] = 0ull; mj1[p] = 0ull; }
    const unsigned int* r0h = sW2h + lane * 132;
    const unsigned int* r1h = sW2h + (lane + 32) * 132;
    #pragma unroll 4
    for (int m4 = 0; m4 < 32; ++m4) {
        uint4 w0 = *(const uint4*)(r0h + 4 * m4);
        uint4 w1 = *(const uint4*)(r1h + 4 * m4);
        u64 w0p[4] = {hpk(w0.x), hpk(w0.y), hpk(w0.z), hpk(w0.w)};
        u64 w1p4[4] = {hpk(w1.x), hpk(w1.y), hpk(w1.z), hpk(w1.w)};
        #pragma unroll
        for (int p = 0; p < P; ++p) {
            const float* uf = (const float*)sA[p];
            float4 ua4 = *(const float4*)(uf + 8 * m4);        // pairs 4m4, 4m4+1
            float4 ub4 = *(const float4*)(uf + 8 * m4 + 4);    // pairs 4m4+2, 4m4+3
            u64 u0 = pk2(ua4.x, ua4.y), u1 = pk2(ua4.z, ua4.w);
            u64 u2v = pk2(ub4.x, ub4.y), u3 = pk2(ub4.z, ub4.w);
            mj0[p] = ffma2(u0, w0p[0], mj0[p]);
            mj0[p] = ffma2(u1, w0p[1], mj0[p]);
            mj0[p] = ffma2(u2v, w0p[2], mj0[p]);
            mj0[p] = ffma2(u3, w0p[3], mj0[p]);
            mj1[p] = ffma2(u0, w1p4[0], mj1[p]);
            mj1[p] = ffma2(u1, w1p4[1], mj1[p]);
            mj1[p] = ffma2(u2v, w1p4[2], mj1[p]);
            mj1[p] = ffma2(u3, w1p4[3], mj1[p]);
        }
    }
    // scr_j = c_j * m_j  (scr aliases sh)
    #pragma unroll
    for (int p = 0; p < P; ++p) {
        float a, b;
        unpk(mj0[p], a, b); sh[p][lane]      = c0[p] * (a + b);
        unpk(mj1[p], a, b); sh[p][lane + 32] = c1[p] * (a + b);
    }
    __syncwarp();

    // ---- s_i = sum_j W1[i,j]*scr[j] (fp16 W1T; contiguous-half split + xor16) ----
    float ssum[P];
    int irow = lane & 15, jo = lane >> 4;
    #pragma unroll
    for (int p = 0; p < P; ++p) {
        u64 s2 = 0ull;
        #pragma unroll
        for (int j2l = 0; j2l < 16; ++j2l) {
            int j2 = jo * 16 + j2l;
            s2 = ffma2(hpk(sW1Th[j2 * 16 + irow]), *(const u64*)&sh[p][2 * j2], s2);
        }
        float sl, shi; unpk(s2, sl, shi);
        float s = sl + shi;
        s += __shfl_xor_sync(FULLMASK, s, 16);
        ssum[p] = s;
    }
    // (factor 2 in s and 1/2 in Gamma cancel: solve g y = s, dv = -y)

    bool lo = lane < 16;
    int  l16 = lane & 15;

    // sysA: pts 0/1 half-packed; sysB: pts 2/3 half-packed
    float ga[16], gb[16];
    #pragma unroll
    for (int t = 0; t < 8; ++t) {
        float a0 = __shfl_xor_sync(FULLMASK, gp[0][t], 16);
        float a1 = __shfl_xor_sync(FULLMASK, gp[1][t], 16);
        float a2 = __shfl_xor_sync(FULLMASK, gp[2][t], 16);
        float a3 = __shfl_xor_sync(FULLMASK, gp[3][t], 16);
        ga[t]     = lo ? gp[0][t] : a1;
        ga[8 + t] = lo ? a0       : gp[1][t];
        gb[t]     = lo ? gp[2][t] : a3;
        gb[8 + t] = lo ? a2       : gp[3][t];
    }
    float ra = lo ? ssum[0] : ssum[1];
    float rb = lo ? ssum[2] : ssum[3];

    float y01, y23;
    solve16_dual(ga, ra, gb, rb, l16, y01, y23);

    // ---- assemble k: lane<16 -> v part, lane>=16 -> dv = -y ----
    kout[0] = __shfl_xor_sync(FULLMASK, lo ? -y01 : zt[0], 16);
    float t1s = __shfl_xor_sync(FULLMASK, zt[1], 16);
    kout[1] = lo ? t1s : -y01;
    kout[2] = __shfl_xor_sync(FULLMASK, lo ? -y23 : zt[2], 16);
    float t3s = __shfl_xor_sync(FULLMASK, zt[3], 16);
    kout[3] = lo ? t3s : -y23;
    __syncwarp();
}

extern __shared__ float smem_dyn[];

__global__ void __launch_bounds__(NWARP * 32, 1)
geo_kernel(const float* __restrict__ z_in,
           const float* __restrict__ t_ptr,
           const float* __restrict__ W1,
           const float* __restrict__ b1,
           const float* __restrict__ W2,
           const float* __restrict__ b2,
           const int*   __restrict__ ns_ptr,
           float* __restrict__ z_out,
           int B)
{
    // Smem map (float-slot units; each u32 array slot = 1 float slot):
    //   sW1h  [0,512)      512 u32
    //   sW1Th [512,1024)   512 u32
    //   sW2h  [1024,9472)  8448 u32 (64 rows * 132)
    //   sb1   [9472,9536)  64 f32
    //   sb2   [9536,9792)  256 f32
    //   ws    [9792, ...)  NWARP*P*WS_PT f32
    unsigned int* sW1h  = (unsigned int*)(smem_dyn);         // half2 (W1[i,l],W1[i,l+32]) at u32-idx i*32+l
    unsigned int* sW1Th = (unsigned int*)(smem_dyn + 512);   // half2 (W1[i,2j2],W1[i,2j2+1]) at u32-idx j2*16+i
    unsigned int* sW2h  = (unsigned int*)(smem_dyn + 1024);  // half2 (W2[j,c],W2[j,c+32]) at u32-idx j*132+m
    float* sb1   = smem_dyn + 9472;   // 64
    float* sb2   = smem_dyn + 9536;   // 256
    float* wsbase = smem_dyn + 9792;  // NWARP * P * WS_PT

    int tid = threadIdx.x;
    const int NT = NWARP * 32;
    // W1 fp16 (col-pair form)
    for (int idx = tid; idx < 512; idx += NT) {
        int i = idx >> 5, l = idx & 31;
        __half2 hh = __halves2half2(__float2half_rn(W1[i * 64 + l]),
                                    __float2half_rn(W1[i * 64 + l + 32]));
        sW1h[i * 32 + l] = *reinterpret_cast<unsigned int*>(&hh);
    }
    // W1 fp16 (transposed-pair form)
    for (int idx = tid; idx < 512; idx += NT) {
        int j2 = idx >> 4, i = idx & 15;
        __half2 hh = __halves2half2(__float2half_rn(W1[i * 64 + 2 * j2]),
                                    __float2half_rn(W1[i * 64 + 2 * j2 + 1]));
        sW1Th[j2 * 16 + i] = *reinterpret_cast<unsigned int*>(&hh);
    }
    // W2 fp16 pair layout
    for (int idx = tid; idx < 64 * 128; idx += NT) {
        int j = idx >> 7, m = idx & 127;
        int c = ((m >> 5) << 6) + (m & 31);
        __half2 hh = __halves2half2(__float2half_rn(W2[j * 256 + c]),
                                    __float2half_rn(W2[j * 256 + c + 32]));
        sW2h[j * 132 + m] = *reinterpret_cast<unsigned int*>(&hh);
    }
    if (tid < 64) sb1[tid] = b1[tid];
    if (tid < 256) sb2[tid] = b2[tid];
    __syncthreads();

    int warp = tid >> 5, lane = tid & 31;
    float* ws = wsbase + warp * (P * WS_PT);

    int pt0 = (blockIdx.x * NWARP + warp) * P;
    float z[P];
    #pragma unroll
    for (int p = 0; p < P; ++p) {
        int pt = pt0 + p;
        z[p] = (pt < B) ? z_in[pt * 32 + lane] : 0.f;
    }

    int ns = ns_ptr[0];
    float dt = t_ptr[0] / (float)ns;

    float kk[P], acc[P], zt[P];
    #pragma unroll 1
    for (int step = 0; step < ns; ++step) {
        #pragma unroll
        for (int p = 0; p < P; ++p) { kk[p] = 0.f; acc[p] = 0.f; }
        #pragma unroll 1
        for (int s = 0; s < 4; ++s) {
            float alpha = (s == 0) ? 0.f : ((s == 3) ? 1.f : 0.5f);
            float wgt   = (s == 1 || s == 2) ? 2.f : 1.f;
            #pragma unroll
            for (int p = 0; p < P; ++p) zt[p] = fmaf(alpha * dt, kk[p], z[p]);
            warp_f4(zt, kk, lane, sW1h, sW1Th, sW2h, sb1, sb2, ws);
            #pragma unroll
            for (int p = 0; p < P; ++p) acc[p] += wgt * kk[p];
        }
        #pragma unroll
        for (int p = 0; p < P; ++p) z[p] = fmaf(dt / 6.f, acc[p], z[p]);
    }

    #pragma unroll
    for (int p = 0; p < P; ++p) {
        int pt = pt0 + p;
        if (pt < B) z_out[pt * 32 + lane] = z[p];
    }
}

extern "C" void kernel_launch(void* const* d_in, const int* in_sizes, int n_in,
                              void* d_out, int out_size)
{
    const float* z  = (const float*)d_in[0];
    const float* t  = (const float*)d_in[1];
    const float* W1 = (const float*)d_in[2];
    const float* b1 = (const float*)d_in[3];
    const float* W2 = (const float*)d_in[4];
    const float* b2 = (const float*)d_in[5];
    const int*   ns = (const int*)d_in[6];
    float* out = (float*)d_out;

    int B = in_sizes[0] / 32;                 // 16384 points
    int smem_bytes = (9792 + NWARP * P * WS_PT) * sizeof(float);  // 125,184 B

    cudaFuncSetAttribute(geo_kernel,
                         cudaFuncAttributeMaxDynamicSharedMemorySize, smem_bytes);

    int pts_per_block = NWARP * P;
    int blocks = (B + pts_per_block - 1) / pts_per_block;
    geo_kernel<<<blocks, NWARP * 32, smem_bytes>>>(z, t, W1, b1, W2, b2, ns, out, B);
}